// round 14
// baseline (speedup 1.0000x reference)
#include <cuda_runtime.h>
#include <cuda_bf16.h>
#include <math.h>
#include <stdint.h>

#define NV    8192
#define FEAT  1024
#define HID   256
#define CLS   16
#define MAXNB 192

// ---------------- device scratch (no allocations allowed) ----------------
__device__ int   g_col[NV * MAXNB];
__device__ float g_adjv[NV * MAXNB];
__device__ int   g_cnt[NV];
__device__ float g_diag[NV];
__device__ float g_P[NV * HID];     // residual stream
__device__ float g_A[NV * HID];     // Wh
__device__ float g_C16[NV * CLS];
__device__ float g_O16[NV * CLS];
__device__ float g_norm2[2 * NV];   // per-column-tile partial sum-of-squares
__device__ float g_t2[NV];
// bf16 hi/lo splits for tensor-core GEMM
__device__ __nv_bfloat16 g_xhi[NV * FEAT];
__device__ __nv_bfloat16 g_xlo[NV * FEAT];
__device__ __nv_bfloat16 g_phi[NV * HID];
__device__ __nv_bfloat16 g_plo[NV * HID];
__device__ __nv_bfloat16 g_whi[2 * HID * FEAT];
__device__ __nv_bfloat16 g_wlo[2 * HID * FEAT];

__device__ __forceinline__ float softplusf(float x) {        // accurate
    return x > 20.f ? x : log1pf(expf(x));
}
__device__ __forceinline__ float softplus_fast(float x) {    // MUFU-based
    return x > 20.f ? x : __logf(1.f + __expf(x));
}
__device__ __forceinline__ float eluf(float x) {
    return x > 0.f ? x : expm1f(x);
}
__device__ __forceinline__ uint32_t smem_to_u32(const void* smem_ptr) {
    uint32_t addr;
    asm("{ .reg .u64 tmp; cvta.to.shared.u64 tmp, %1; cvt.u32.u64 %0, tmp; }"
        : "=r"(addr) : "l"(smem_ptr));
    return addr;
}
__device__ __forceinline__ void cp16(uint32_t dst, const void* src) {
    asm volatile("cp.async.cg.shared.global [%0], [%1], 16;"
                 :: "r"(dst), "l"(src) : "memory");
}
#define CP_COMMIT() asm volatile("cp.async.commit_group;" ::: "memory")
#define CP_WAIT0()  asm volatile("cp.async.wait_group 0;" ::: "memory")
#define CP_WAIT1()  asm volatile("cp.async.wait_group 1;" ::: "memory")

__device__ __forceinline__ void mma16816(float* d, const uint32_t* a, const uint32_t* b) {
    asm volatile(
        "mma.sync.aligned.m16n8k16.row.col.f32.bf16.bf16.f32 "
        "{%0,%1,%2,%3}, {%4,%5,%6,%7}, {%8,%9}, {%0,%1,%2,%3};"
        : "+f"(d[0]), "+f"(d[1]), "+f"(d[2]), "+f"(d[3])
        : "r"(a[0]), "r"(a[1]), "r"(a[2]), "r"(a[3]), "r"(b[0]), "r"(b[1]));
}
__device__ __forceinline__ void ldsm_x4(uint32_t* r, uint32_t addr) {
    asm volatile("ldmatrix.sync.aligned.m8n8.x4.shared.b16 {%0,%1,%2,%3}, [%4];"
        : "=r"(r[0]), "=r"(r[1]), "=r"(r[2]), "=r"(r[3]) : "r"(addr));
}

// ---------------- CSR build from dense adjacency (OR-tree fast scan) ----------------
__device__ __forceinline__ void csr_extract(int i, int cbase, uint4 u, int* cnt) {
    uint32_t v0 = u.x, v1 = u.y, v2 = u.z, v3 = u.w;
    if (v0) { int p = atomicAdd(cnt, 1); if (p < MAXNB) { g_col[i * MAXNB + p] = cbase + 0; g_adjv[i * MAXNB + p] = __uint_as_float(v0); } }
    if (v1) { int p = atomicAdd(cnt, 1); if (p < MAXNB) { g_col[i * MAXNB + p] = cbase + 1; g_adjv[i * MAXNB + p] = __uint_as_float(v1); } }
    if (v2) { int p = atomicAdd(cnt, 1); if (p < MAXNB) { g_col[i * MAXNB + p] = cbase + 2; g_adjv[i * MAXNB + p] = __uint_as_float(v2); } }
    if (v3) { int p = atomicAdd(cnt, 1); if (p < MAXNB) { g_col[i * MAXNB + p] = cbase + 3; g_adjv[i * MAXNB + p] = __uint_as_float(v3); } }
}

__global__ __launch_bounds__(256) void k_build_csr(const float* __restrict__ adj) {
    int i = blockIdx.x;
    __shared__ int cnt;
    if (threadIdx.x == 0) {
        cnt = 0;
        g_diag[i] = adj[(size_t)i * NV + i];
    }
    __syncthreads();
    const uint4* row = reinterpret_cast<const uint4*>(adj + (size_t)i * NV);
    int tid = threadIdx.x;
#pragma unroll
    for (int it = 0; it < 2; it++) {
        int c0 = tid + (it * 4 + 0) * 256;
        int c1 = tid + (it * 4 + 1) * 256;
        int c2 = tid + (it * 4 + 2) * 256;
        int c3 = tid + (it * 4 + 3) * 256;
        uint4 u0 = __ldcs(&row[c0]);
        uint4 u1 = __ldcs(&row[c1]);
        uint4 u2 = __ldcs(&row[c2]);
        uint4 u3 = __ldcs(&row[c3]);
        uint32_t m = (u0.x | u0.y | u0.z) | (u0.w | u1.x | u1.y) |
                     (u1.z | u1.w | u2.x) | (u2.y | u2.z | u2.w) |
                     (u3.x | u3.y | u3.z) | u3.w;
        if (m) {
            csr_extract(i, c0 * 4, u0, &cnt);
            csr_extract(i, c1 * 4, u1, &cnt);
            csr_extract(i, c2 * 4, u2, &cnt);
            csr_extract(i, c3 * 4, u3, &cnt);
        }
    }
    __syncthreads();
    if (threadIdx.x == 0) g_cnt[i] = cnt < MAXNB ? cnt : MAXNB;
}

// ---------------- fused prologue splits: x, fcnW, W0 ----------------
__device__ __forceinline__ void split_store(float4 v, __nv_bfloat16* hi,
                                            __nv_bfloat16* lo, int idx) {
    float xs[4] = {v.x, v.y, v.z, v.w};
    __nv_bfloat16 h[4], l[4];
#pragma unroll
    for (int q = 0; q < 4; q++) {
        h[q] = __float2bfloat16(xs[q]);
        l[q] = __float2bfloat16(xs[q] - __bfloat162float(h[q]));
    }
    __nv_bfloat162* hp = reinterpret_cast<__nv_bfloat162*>(hi) + idx * 2;
    __nv_bfloat162* lp = reinterpret_cast<__nv_bfloat162*>(lo) + idx * 2;
    hp[0] = __nv_bfloat162(h[0], h[1]); hp[1] = __nv_bfloat162(h[2], h[3]);
    lp[0] = __nv_bfloat162(l[0], l[1]); lp[1] = __nv_bfloat162(l[2], l[3]);
}

#define NX4 (NV * FEAT / 4)
#define NW4 (HID * FEAT / 4)

__global__ void k_prep(const float* __restrict__ x, const float* __restrict__ fcnW,
                       const float* __restrict__ W0,
                       __nv_bfloat16* __restrict__ xhi, __nv_bfloat16* __restrict__ xlo,
                       __nv_bfloat16* __restrict__ whi, __nv_bfloat16* __restrict__ wlo) {
    int idx = blockIdx.x * 256 + threadIdx.x;
    if (idx < NX4) {
        float4 v = __ldcs(reinterpret_cast<const float4*>(x) + idx);
        split_store(v, xhi, xlo, idx);
    } else if (idx < NX4 + 2 * NW4) {
        int k = idx - NX4;
        const float* S = (k < NW4) ? fcnW : W0;
        int src = (k < NW4) ? k : k - NW4;
        float4 v = __ldcs(reinterpret_cast<const float4*>(S) + src);
        split_store(v, whi, wlo, k);
    }
}

// W1 split
__global__ void k_split(const float* __restrict__ X,
                        __nv_bfloat16* __restrict__ hi,
                        __nv_bfloat16* __restrict__ lo, int n4) {
    int idx = blockIdx.x * 256 + threadIdx.x;
    if (idx >= n4) return;
    float4 v = __ldcs(reinterpret_cast<const float4*>(X) + idx);
    split_store(v, hi, lo, idx);
}

// ---------------- mma.sync bf16 GEMM, fused 3xBF16 products ----------------
#define G_ROWB   80
#define F_TILE   (128 * G_ROWB)   // 10240
#define F_STAGE  (4 * F_TILE)     // 40960 (Ah|Al|Bh|Bl)
#define F_SMEM   (2 * F_STAGE)    // 81920

__global__ __launch_bounds__(256, 2)
void k_mma_gemm(const __nv_bfloat16* __restrict__ Ah, const __nv_bfloat16* __restrict__ Al,
                const __nv_bfloat16* __restrict__ Bh, const __nv_bfloat16* __restrict__ Bl,
                const float* __restrict__ biasa, const float* __restrict__ biasb,
                float* __restrict__ Ca, float* __restrict__ Cb,
                int K, int elu_split)
{
    extern __shared__ char smem[];
    uint32_t sb = smem_to_u32(smem);
    int tid = threadIdx.x;
    int wid = tid >> 5, lane = tid & 31;
    int wm = wid >> 2, wn = wid & 3;
    int gid = lane >> 2, tk = (lane & 3) * 2;
    int bm = blockIdx.x * 128, bnw = blockIdx.y * 128;

    uint32_t a_lane = (uint32_t)(((lane & 7) + ((lane >> 3) & 1) * 8) * G_ROWB
                                 + (lane >> 4) * 16);
    uint32_t b_lane = (uint32_t)(((lane & 7) + (lane >> 4) * 8) * G_ROWB
                                 + ((lane >> 3) & 1) * 16);

    float d[4][4][4];
#pragma unroll
    for (int ma = 0; ma < 4; ma++)
#pragma unroll
        for (int na = 0; na < 4; na++)
#pragma unroll
            for (int q = 0; q < 4; q++) d[ma][na][q] = 0.f;

    int NC = K / 32;
    int lrow = tid >> 2, lq = tid & 3;
    uint32_t lso  = (uint32_t)(lrow * G_ROWB + lq * 16);
    uint32_t lso2 = (uint32_t)((lrow + 64) * G_ROWB + lq * 16);

#define ISSUE_CHUNK(c_) do {                                                        \
        int k0_ = (c_) * 32;                                                        \
        uint32_t sst_ = sb + ((c_) & 1) * F_STAGE;                                  \
        cp16(sst_ + lso,                Ah + (size_t)(bm + lrow) * K + k0_ + lq * 8);        \
        cp16(sst_ + lso2,               Ah + (size_t)(bm + lrow + 64) * K + k0_ + lq * 8);   \
        cp16(sst_ + F_TILE + lso,       Al + (size_t)(bm + lrow) * K + k0_ + lq * 8);        \
        cp16(sst_ + F_TILE + lso2,      Al + (size_t)(bm + lrow + 64) * K + k0_ + lq * 8);   \
        cp16(sst_ + 2 * F_TILE + lso,   Bh + (size_t)(bnw + lrow) * K + k0_ + lq * 8);       \
        cp16(sst_ + 2 * F_TILE + lso2,  Bh + (size_t)(bnw + lrow + 64) * K + k0_ + lq * 8);  \
        cp16(sst_ + 3 * F_TILE + lso,   Bl + (size_t)(bnw + lrow) * K + k0_ + lq * 8);       \
        cp16(sst_ + 3 * F_TILE + lso2,  Bl + (size_t)(bnw + lrow + 64) * K + k0_ + lq * 8);  \
        CP_COMMIT();                                                                \
    } while (0)

    ISSUE_CHUNK(0);

    for (int c = 0; c < NC; c++) {
        if (c + 1 < NC) { ISSUE_CHUNK(c + 1); CP_WAIT1(); }
        else { CP_WAIT0(); }
        __syncthreads();

        uint32_t st = sb + (c & 1) * F_STAGE;
        uint32_t sAh = st, sAl = st + F_TILE;
        uint32_t sBh = st + 2 * F_TILE, sBl = st + 3 * F_TILE;

#pragma unroll
        for (int kk2 = 0; kk2 < 2; kk2++) {
            uint32_t ko = (uint32_t)(kk2 * 32);
            uint32_t bh[4][2], bl[4][2];
#pragma unroll
            for (int p = 0; p < 2; p++) {
                uint32_t boff = (uint32_t)((wn * 32 + p * 16) * G_ROWB) + ko + b_lane;
                uint32_t rh[4], rl[4];
                ldsm_x4(rh, sBh + boff);
                ldsm_x4(rl, sBl + boff);
                bh[p * 2][0] = rh[0]; bh[p * 2][1] = rh[1];
                bh[p * 2 + 1][0] = rh[2]; bh[p * 2 + 1][1] = rh[3];
                bl[p * 2][0] = rl[0]; bl[p * 2][1] = rl[1];
                bl[p * 2 + 1][0] = rl[2]; bl[p * 2 + 1][1] = rl[3];
            }
#pragma unroll
            for (int ma = 0; ma < 4; ma++) {
                uint32_t aoff = (uint32_t)((wm * 64 + ma * 16) * G_ROWB) + ko + a_lane;
                uint32_t ah[4], al[4];
                ldsm_x4(ah, sAh + aoff);
                ldsm_x4(al, sAl + aoff);
#pragma unroll
                for (int na = 0; na < 4; na++) {
                    mma16816(d[ma][na], ah, bh[na]);
                    mma16816(d[ma][na], ah, bl[na]);
                    mma16816(d[ma][na], al, bh[na]);
                }
            }
        }
        __syncthreads();
    }

    // epilogue (+ fused row sum-of-squares partials for non-elu tiles)
    bool first = (blockIdx.y < (unsigned)elu_split);
    float* C = first ? Ca : Cb;
    const float* bias = first ? biasa : biasb;
    int coloff = first ? bnw : bnw - elu_split * 128;
    float rs0[4], rs1[4];
#pragma unroll
    for (int ma = 0; ma < 4; ma++) { rs0[ma] = 0.f; rs1[ma] = 0.f; }
#pragma unroll
    for (int ma = 0; ma < 4; ma++) {
        int r0 = bm + wm * 64 + ma * 16 + gid;
#pragma unroll
        for (int na = 0; na < 4; na++) {
            int col = coloff + wn * 32 + na * 8 + tk;
            float b0 = bias[col], b1 = bias[col + 1];
            float v0 = d[ma][na][0] + b0, v1 = d[ma][na][1] + b1;
            float v2 = d[ma][na][2] + b0, v3 = d[ma][na][3] + b1;
            if (first) { v0 = eluf(v0); v1 = eluf(v1); v2 = eluf(v2); v3 = eluf(v3); }
            rs0[ma] += v0 * v0 + v1 * v1;
            rs1[ma] += v2 * v2 + v3 * v3;
            *reinterpret_cast<float2*>(C + (size_t)r0 * 256 + col)       = make_float2(v0, v1);
            *reinterpret_cast<float2*>(C + (size_t)(r0 + 8) * 256 + col) = make_float2(v2, v3);
        }
    }
    if (!first) {
        float* parts = reinterpret_cast<float*>(smem);   // [4][128]
#pragma unroll
        for (int ma = 0; ma < 4; ma++) {
            float s0 = rs0[ma], s1 = rs1[ma];
            s0 += __shfl_xor_sync(0xffffffffu, s0, 1);
            s0 += __shfl_xor_sync(0xffffffffu, s0, 2);
            s1 += __shfl_xor_sync(0xffffffffu, s1, 1);
            s1 += __shfl_xor_sync(0xffffffffu, s1, 2);
            if ((lane & 3) == 0) {
                int r = wm * 64 + ma * 16 + gid;
                parts[wn * 128 + r] = s0;
                parts[wn * 128 + r + 8] = s1;
            }
        }
        __syncthreads();
        if (tid < 128) {
            float t = parts[tid] + parts[128 + tid] + parts[256 + tid] + parts[384 + tid];
            g_norm2[(size_t)(blockIdx.y - elu_split) * NV + bm + tid] = t;
        }
    }
#undef ISSUE_CHUNK
}

// ---------------- small GEMM for layer 2 (Nc=16) + fused norm partials ----------------
__global__ __launch_bounds__(256) void k_gemm_small(
    const float* __restrict__ A, const float* __restrict__ W,
    const float* __restrict__ bias, float* __restrict__ C,
    int M, int Nc, int K)
{
    __shared__ float Ws[CLS][HID];
    int tid = threadIdx.x;
    for (int idx = tid; idx < Nc * K; idx += 256)
        Ws[idx / K][idx % K] = W[idx];
    __syncthreads();
    int row = blockIdx.x * 8 + (tid >> 5);
    int lane = tid & 31;
    const float4* ap = reinterpret_cast<const float4*>(A + (size_t)row * K);
    float4 a0 = ap[lane];
    float4 a1 = ap[lane + 32];
    float accv[CLS];
    float sumsq = 0.f;
#pragma unroll
    for (int c = 0; c < CLS; c++) {
        float4 w0 = *reinterpret_cast<const float4*>(&Ws[c][lane * 4]);
        float4 w1 = *reinterpret_cast<const float4*>(&Ws[c][lane * 4 + 128]);
        float s = a0.x * w0.x + a0.y * w0.y + a0.z * w0.z + a0.w * w0.w
                + a1.x * w1.x + a1.y * w1.y + a1.z * w1.z + a1.w * w1.w;
#pragma unroll
        for (int o = 16; o; o >>= 1) s += __shfl_xor_sync(0xffffffffu, s, o);
        accv[c] = s + bias[c];
        sumsq += accv[c] * accv[c];
    }
    if (lane < CLS) C[(size_t)row * CLS + lane] = accv[lane];
    if (lane == 0) { g_norm2[row] = sumsq; g_norm2[NV + row] = 0.f; }
}

// ---------------- sparse attention + aggregation: WARP PER ROW, pipelined ----------------
template<int D, bool RES, bool SPLIT>
__global__ __launch_bounds__(256) void k_sparse(
    const float* __restrict__ Wh, float* __restrict__ out,
    const float* __restrict__ dc, const float* __restrict__ co,
    const float* __restrict__ sp, float coef,
    __nv_bfloat16* __restrict__ phi, __nv_bfloat16* __restrict__ plo)
{
    int i = blockIdx.x * 8 + (threadIdx.x >> 5);
    int lane = threadIdx.x & 31;

    float nsqi = g_norm2[i] + g_norm2[NV + i];
    float diag = g_diag[i];
    float dc0 = dc[0], dc1 = dc[1];
    float cm = fmaxf(co[0], fmaxf(co[1], co[2]));
    float ce0 = __expf(co[0] - cm), ce1 = __expf(co[1] - cm), ce2 = __expf(co[2] - cm);
    float cden = ce0 + ce1 + ce2;
    float s = softplusf(sp[0]);
    float c0s = s * ce0 / cden, c1s = s * ce1 / cden, c2s = s * ce2 / cden;
    int nn = g_cnt[i];
    int base = i * MAXNB;

    if constexpr (D == 256) {
        const float4* wip = reinterpret_cast<const float4*>(Wh + (size_t)i * D);
        float4 wi0 = wip[lane], wi1 = wip[lane + 32];
        float4 ac0 = make_float4(0, 0, 0, 0), ac1 = ac0;

        // pipeline state: current pair
        int j0, j1; float a0, a1, nsq0, nsq1; bool h1c;
        float4 u0, u1, q0, q1;
        {
            h1c = 1 < nn;
            int o0 = base;
            int o1 = base + (h1c ? 1 : 0);
            j0 = g_col[o0]; a0 = g_adjv[o0];
            j1 = g_col[o1]; a1 = g_adjv[o1];
            const float4* wj0 = reinterpret_cast<const float4*>(Wh + (size_t)j0 * D);
            const float4* wj1 = reinterpret_cast<const float4*>(Wh + (size_t)j1 * D);
            u0 = wj0[lane]; u1 = wj0[lane + 32];
            q0 = wj1[lane]; q1 = wj1[lane + 32];
            nsq0 = g_norm2[j0] + g_norm2[NV + j0];
            nsq1 = g_norm2[j1] + g_norm2[NV + j1];
        }

        for (int t = 0; t < nn; t += 2) {
            // prefetch next pair
            int jn0 = 0, jn1 = 0; float an0 = 1.f, an1 = 1.f, nn0 = 0.f, nn1 = 0.f;
            bool hn1 = false;
            float4 v0, v1, r0, r1;
            int tn = t + 2;
            bool more = tn < nn;
            if (more) {
                hn1 = tn + 1 < nn;
                int o0 = base + tn;
                int o1 = base + (hn1 ? tn + 1 : tn);
                jn0 = g_col[o0]; an0 = g_adjv[o0];
                jn1 = g_col[o1]; an1 = g_adjv[o1];
                const float4* wj0 = reinterpret_cast<const float4*>(Wh + (size_t)jn0 * D);
                const float4* wj1 = reinterpret_cast<const float4*>(Wh + (size_t)jn1 * D);
                v0 = wj0[lane]; v1 = wj0[lane + 32];
                r0 = wj1[lane]; r1 = wj1[lane + 32];
                nn0 = g_norm2[jn0] + g_norm2[NV + jn0];
                nn1 = g_norm2[jn1] + g_norm2[NV + jn1];
            }
            // process current pair
            float p0 = wi0.x * u0.x + wi0.y * u0.y + wi0.z * u0.z + wi0.w * u0.w
                     + wi1.x * u1.x + wi1.y * u1.y + wi1.z * u1.z + wi1.w * u1.w;
            float p1 = wi0.x * q0.x + wi0.y * q0.y + wi0.z * q0.z + wi0.w * q0.w
                     + wi1.x * q1.x + wi1.y * q1.y + wi1.z * q1.z + wi1.w * q1.w;
#pragma unroll
            for (int o = 16; o; o >>= 1) {
                p0 += __shfl_xor_sync(0xffffffffu, p0, o);
                p1 += __shfl_xor_sync(0xffffffffu, p1, o);
            }
            float e0 = p0 * rsqrtf(fmaxf(nsqi * nsq0, 1e-18f));
            float e1 = p1 * rsqrtf(fmaxf(nsqi * nsq1, 1e-18f));
            float sc0 = softplus_fast(dc0 * (__fdividef(diag, a0) - 1.f) + dc1);
            float sc1 = softplus_fast(dc0 * (__fdividef(diag, a1) - 1.f) + dc1);
            float att0 = (j0 == i) ? 0.f : e0 * a0 * sc0;
            float att1 = (j1 == i || !h1c) ? 0.f : e1 * a1 * sc1;
            float wg0 = c0s * fmaxf(att0, 0.f) + c1s * fminf(att0, 0.f);
            float wg1 = c0s * fmaxf(att1, 0.f) + c1s * fminf(att1, 0.f);
            ac0.x += wg0 * u0.x + wg1 * q0.x; ac0.y += wg0 * u0.y + wg1 * q0.y;
            ac0.z += wg0 * u0.z + wg1 * q0.z; ac0.w += wg0 * u0.w + wg1 * q0.w;
            ac1.x += wg0 * u1.x + wg1 * q1.x; ac1.y += wg0 * u1.y + wg1 * q1.y;
            ac1.z += wg0 * u1.z + wg1 * q1.z; ac1.w += wg0 * u1.w + wg1 * q1.w;
            // rotate
            if (more) {
                j0 = jn0; j1 = jn1; a0 = an0; a1 = an1;
                nsq0 = nn0; nsq1 = nn1; h1c = hn1;
                u0 = v0; u1 = v1; q0 = r0; q1 = r1;
            }
        }

        float o0[4] = {ac0.x + c2s * wi0.x, ac0.y + c2s * wi0.y,
                       ac0.z + c2s * wi0.z, ac0.w + c2s * wi0.w};
        float o1[4] = {ac1.x + c2s * wi1.x, ac1.y + c2s * wi1.y,
                       ac1.z + c2s * wi1.z, ac1.w + c2s * wi1.w};
        size_t rbase = (size_t)i * D + lane * 4;
        if (RES) {
            float4 P0 = *reinterpret_cast<float4*>(out + rbase);
            float4 P1 = *reinterpret_cast<float4*>(out + rbase + 128);
            float n0[4] = {P0.x + coef * eluf(o0[0]), P0.y + coef * eluf(o0[1]),
                           P0.z + coef * eluf(o0[2]), P0.w + coef * eluf(o0[3])};
            float n1[4] = {P1.x + coef * eluf(o1[0]), P1.y + coef * eluf(o1[1]),
                           P1.z + coef * eluf(o1[2]), P1.w + coef * eluf(o1[3])};
            *reinterpret_cast<float4*>(out + rbase)       = make_float4(n0[0], n0[1], n0[2], n0[3]);
            *reinterpret_cast<float4*>(out + rbase + 128) = make_float4(n1[0], n1[1], n1[2], n1[3]);
            if (SPLIT) {
#pragma unroll
                for (int g = 0; g < 2; g++) {
                    const float* nv = g ? n1 : n0;
                    size_t off = rbase + g * 128;
                    __nv_bfloat16 h[4], l[4];
#pragma unroll
                    for (int q = 0; q < 4; q++) {
                        h[q] = __float2bfloat16(nv[q]);
                        l[q] = __float2bfloat16(nv[q] - __bfloat162float(h[q]));
                    }
                    __nv_bfloat162* hp = reinterpret_cast<__nv_bfloat162*>(phi + off);
                    __nv_bfloat162* lp = reinterpret_cast<__nv_bfloat162*>(plo + off);
                    hp[0] = __nv_bfloat162(h[0], h[1]); hp[1] = __nv_bfloat162(h[2], h[3]);
                    lp[0] = __nv_bfloat162(l[0], l[1]); lp[1] = __nv_bfloat162(l[2], l[3]);
                }
            }
        } else {
            *reinterpret_cast<float4*>(out + rbase)       = make_float4(o0[0], o0[1], o0[2], o0[3]);
            *reinterpret_cast<float4*>(out + rbase + 128) = make_float4(o1[0], o1[1], o1[2], o1[3]);
        }
    } else {
        // D == 16: lanes 0-15 own one dim each
        float wi = (lane < D) ? Wh[(size_t)i * D + lane] : 0.f;
        float ac = 0.f;
        for (int t = 0; t < nn; t++) {
            int j = g_col[base + t];
            float a = g_adjv[base + t];
            float v = (lane < D) ? Wh[(size_t)j * D + lane] : 0.f;
            float p = wi * v;
#pragma unroll
            for (int o = 16; o; o >>= 1) p += __shfl_xor_sync(0xffffffffu, p, o);
            float nsq = g_norm2[j] + g_norm2[NV + j];
            float e = p * rsqrtf(fmaxf(nsqi * nsq, 1e-18f));
            float sc = softplus_fast(dc0 * (__fdividef(diag, a) - 1.f) + dc1);
            float att = (j != i) ? e * a * sc : 0.f;
            float wgt = c0s * fmaxf(att, 0.f) + c1s * fminf(att, 0.f);
            ac += wgt * v;
        }
        if (lane < D) {
            float outv = ac + c2s * wi;
            out[(size_t)i * D + lane] = outv;
        }
    }
}

// ---------------- head: log_softmax + softmax + top2 ----------------
__global__ void k_head(const float* __restrict__ C, float* __restrict__ logp,
                       float* __restrict__ pred) {
    int g = threadIdx.x >> 4;
    int l = threadIdx.x & 15;
    int row = blockIdx.x * 16 + g;
    float x = C[row * CLS + l];
    float m = x;
#pragma unroll
    for (int o = 8; o; o >>= 1) m = fmaxf(m, __shfl_xor_sync(0xffffffffu, m, o, 16));
    float ex = expf(x - m);
    float se = ex;
#pragma unroll
    for (int o = 8; o; o >>= 1) se += __shfl_xor_sync(0xffffffffu, se, o, 16);
    float lse = logf(se);
    logp[row * CLS + l] = x - m - lse;
    float pr = ex / se;
    pred[row * CLS + l] = pr;
    int laneid = threadIdx.x & 31;
    int segbase = laneid & 16;
    float m1 = -1.f, m2 = -1.f;
#pragma unroll
    for (int k = 0; k < 16; k++) {
        float v = __shfl_sync(0xffffffffu, pr, segbase + k);
        if (v > m1) { m2 = m1; m1 = v; }
        else if (v > m2) m2 = v;
    }
    if (l == 0) g_t2[row] = m1 + m2;
}

// ---------------- deterministic calib reduction ----------------
__global__ void k_calib(float* __restrict__ out_calib) {
    __shared__ float sh[256];
    float s = 0.f;
    for (int i = threadIdx.x; i < NV; i += 256) s += g_t2[i];
    sh[threadIdx.x] = s;
    __syncthreads();
    for (int o = 128; o; o >>= 1) {
        if (threadIdx.x < o) sh[threadIdx.x] += sh[threadIdx.x + o];
        __syncthreads();
    }
    if (threadIdx.x == 0) out_calib[0] = sh[0] / (float)NV;
}

// ---------------- launcher ----------------
extern "C" void kernel_launch(void* const* d_in, const int* in_sizes, int n_in,
                              void* d_out, int out_size) {
    const float* x    = (const float*)d_in[0];
    const float* adj  = (const float*)d_in[1];
    const float* fcnW = (const float*)d_in[2];
    const float* fcnb = (const float*)d_in[3];
    const float* W0   = (const float*)d_in[4];
    const float* b0   = (const float*)d_in[5];
    const float* dc0  = (const float*)d_in[6];
    const float* c0   = (const float*)d_in[7];
    const float* s0   = (const float*)d_in[8];
    const float* W1   = (const float*)d_in[9];
    const float* b1   = (const float*)d_in[10];
    const float* dc1  = (const float*)d_in[11];
    const float* c1   = (const float*)d_in[12];
    const float* s1   = (const float*)d_in[13];
    const float* W2   = (const float*)d_in[14];
    const float* b2   = (const float*)d_in[15];
    const float* dc2  = (const float*)d_in[16];
    const float* c2   = (const float*)d_in[17];
    const float* s2   = (const float*)d_in[18];

    float* out       = (float*)d_out;
    float* out_logp  = out;
    float* out_calib = out + NV * CLS;
    float* out_pred  = out + NV * CLS + 1;

    float *pP, *pA, *pC16, *pO16;
    cudaGetSymbolAddress((void**)&pP,   g_P);
    cudaGetSymbolAddress((void**)&pA,   g_A);
    cudaGetSymbolAddress((void**)&pC16, g_C16);
    cudaGetSymbolAddress((void**)&pO16, g_O16);
    __nv_bfloat16 *pxh, *pxl, *pph, *ppl, *pwh, *pwl;
    cudaGetSymbolAddress((void**)&pxh, g_xhi);
    cudaGetSymbolAddress((void**)&pxl, g_xlo);
    cudaGetSymbolAddress((void**)&pph, g_phi);
    cudaGetSymbolAddress((void**)&ppl, g_plo);
    cudaGetSymbolAddress((void**)&pwh, g_whi);
    cudaGetSymbolAddress((void**)&pwl, g_wlo);

    cudaFuncSetAttribute(k_mma_gemm, cudaFuncAttributeMaxDynamicSharedMemorySize, F_SMEM);

    // 0: fused splits (x, fcnW, W0)
    k_prep<<<(NX4 + 2 * NW4 + 255) / 256, 256>>>(x, fcnW, W0, pxh, pxl, pwh, pwl);

    // 1: merged GEMM: prev = elu(x@fcnW^T+fcnb)  AND  Wh0 = x@W0^T+b0 (+norm partials)
    k_mma_gemm<<<dim3(NV / 128, 4), 256, F_SMEM>>>(pxh, pxl, pwh, pwl,
                                                   fcnb, b0, pP, pA, FEAT, 2);

    // 2: CSR from adjacency (also extracts diag)
    k_build_csr<<<NV, 256>>>(adj);

    // 3 (PROFILED): layer 0 sparse (warp-per-row, pipelined)
    k_sparse<HID, true, true><<<NV / 8, 256>>>(pA, pP, dc0, c0, s0, 1.0f, pph, ppl);

    // ---- layer 1 (input prev) ----
    k_split<<<(HID * HID / 4 + 255) / 256, 256>>>(W1, pwh, pwl, HID * HID / 4);
    k_mma_gemm<<<dim3(NV / 128, 2), 256, F_SMEM>>>(pph, ppl, pwh, pwl,
                                                   b1, b1, pA, pA, HID, 0);
    float decay = (float)log(0.9 / 27.0 + 1.0);
    k_sparse<HID, true, false><<<NV / 8, 256>>>(pA, pP, dc1, c1, s1, decay, pph, ppl);

    // ---- layer 2 (input prev, D=16; norm fused into small GEMM) ----
    k_gemm_small<<<NV / 8, 256>>>(pP, W2, b2, pC16, NV, CLS, HID);
    k_sparse<CLS, false, false><<<NV / 8, 256>>>(pC16, pO16, dc2, c2, s2, 0.0f, pph, ppl);

    // ---- head ----
    k_head<<<NV / 16, 256>>>(pO16, out_logp, out_pred);
    k_calib<<<1, 256>>>(out_calib);
}

// round 15
// speedup vs baseline: 1.0695x; 1.0695x over previous
#include <cuda_runtime.h>
#include <cuda_bf16.h>
#include <math.h>
#include <stdint.h>

#define NV    8192
#define FEAT  1024
#define HID   256
#define CLS   16
#define MAXNB 192

// ---------------- device scratch (no allocations allowed) ----------------
__device__ int   g_col[NV * MAXNB];
__device__ float g_adjv[NV * MAXNB];
__device__ int   g_cnt[NV];
__device__ float g_diag[NV];
__device__ float g_P[NV * HID];     // residual stream
__device__ float g_A[NV * HID];     // Wh
__device__ float g_C16[NV * CLS];
__device__ float g_O16[NV * CLS];
__device__ float g_norm2[2 * NV];   // per-column-tile partial sum-of-squares
__device__ float g_t2[NV];
// bf16 hi/lo splits for tensor-core GEMM
__device__ __nv_bfloat16 g_xhi[NV * FEAT];
__device__ __nv_bfloat16 g_xlo[NV * FEAT];
__device__ __nv_bfloat16 g_phi[NV * HID];
__device__ __nv_bfloat16 g_plo[NV * HID];
__device__ __nv_bfloat16 g_whi[2 * HID * FEAT];
__device__ __nv_bfloat16 g_wlo[2 * HID * FEAT];

__device__ __forceinline__ float softplusf(float x) {        // accurate
    return x > 20.f ? x : log1pf(expf(x));
}
__device__ __forceinline__ float softplus_fast(float x) {    // MUFU-based
    return x > 20.f ? x : __logf(1.f + __expf(x));
}
__device__ __forceinline__ float eluf(float x) {
    return x > 0.f ? x : expm1f(x);
}
__device__ __forceinline__ uint32_t smem_to_u32(const void* smem_ptr) {
    uint32_t addr;
    asm("{ .reg .u64 tmp; cvta.to.shared.u64 tmp, %1; cvt.u32.u64 %0, tmp; }"
        : "=r"(addr) : "l"(smem_ptr));
    return addr;
}
__device__ __forceinline__ void cp16(uint32_t dst, const void* src) {
    asm volatile("cp.async.cg.shared.global [%0], [%1], 16;"
                 :: "r"(dst), "l"(src) : "memory");
}
#define CP_COMMIT() asm volatile("cp.async.commit_group;" ::: "memory")
#define CP_WAIT0()  asm volatile("cp.async.wait_group 0;" ::: "memory")
#define CP_WAIT1()  asm volatile("cp.async.wait_group 1;" ::: "memory")

__device__ __forceinline__ void mma16816(float* d, const uint32_t* a, const uint32_t* b) {
    asm volatile(
        "mma.sync.aligned.m16n8k16.row.col.f32.bf16.bf16.f32 "
        "{%0,%1,%2,%3}, {%4,%5,%6,%7}, {%8,%9}, {%0,%1,%2,%3};"
        : "+f"(d[0]), "+f"(d[1]), "+f"(d[2]), "+f"(d[3])
        : "r"(a[0]), "r"(a[1]), "r"(a[2]), "r"(a[3]), "r"(b[0]), "r"(b[1]));
}
__device__ __forceinline__ void ldsm_x4(uint32_t* r, uint32_t addr) {
    asm volatile("ldmatrix.sync.aligned.m8n8.x4.shared.b16 {%0,%1,%2,%3}, [%4];"
        : "=r"(r[0]), "=r"(r[1]), "=r"(r[2]), "=r"(r[3]) : "r"(addr));
}

// ---------------- CSR build from dense adjacency (OR-tree fast scan) ----------------
__device__ __forceinline__ void csr_extract(int i, int cbase, uint4 u, int* cnt) {
    uint32_t v0 = u.x, v1 = u.y, v2 = u.z, v3 = u.w;
    if (v0) { int p = atomicAdd(cnt, 1); if (p < MAXNB) { g_col[i * MAXNB + p] = cbase + 0; g_adjv[i * MAXNB + p] = __uint_as_float(v0); } }
    if (v1) { int p = atomicAdd(cnt, 1); if (p < MAXNB) { g_col[i * MAXNB + p] = cbase + 1; g_adjv[i * MAXNB + p] = __uint_as_float(v1); } }
    if (v2) { int p = atomicAdd(cnt, 1); if (p < MAXNB) { g_col[i * MAXNB + p] = cbase + 2; g_adjv[i * MAXNB + p] = __uint_as_float(v2); } }
    if (v3) { int p = atomicAdd(cnt, 1); if (p < MAXNB) { g_col[i * MAXNB + p] = cbase + 3; g_adjv[i * MAXNB + p] = __uint_as_float(v3); } }
}

__global__ __launch_bounds__(256) void k_build_csr(const float* __restrict__ adj) {
    int i = blockIdx.x;
    __shared__ int cnt;
    if (threadIdx.x == 0) {
        cnt = 0;
        g_diag[i] = adj[(size_t)i * NV + i];
    }
    __syncthreads();
    const uint4* row = reinterpret_cast<const uint4*>(adj + (size_t)i * NV);
    int tid = threadIdx.x;
#pragma unroll
    for (int it = 0; it < 2; it++) {
        int c0 = tid + (it * 4 + 0) * 256;
        int c1 = tid + (it * 4 + 1) * 256;
        int c2 = tid + (it * 4 + 2) * 256;
        int c3 = tid + (it * 4 + 3) * 256;
        uint4 u0 = __ldcs(&row[c0]);
        uint4 u1 = __ldcs(&row[c1]);
        uint4 u2 = __ldcs(&row[c2]);
        uint4 u3 = __ldcs(&row[c3]);
        uint32_t m = (u0.x | u0.y | u0.z) | (u0.w | u1.x | u1.y) |
                     (u1.z | u1.w | u2.x) | (u2.y | u2.z | u2.w) |
                     (u3.x | u3.y | u3.z) | u3.w;
        if (m) {
            csr_extract(i, c0 * 4, u0, &cnt);
            csr_extract(i, c1 * 4, u1, &cnt);
            csr_extract(i, c2 * 4, u2, &cnt);
            csr_extract(i, c3 * 4, u3, &cnt);
        }
    }
    __syncthreads();
    if (threadIdx.x == 0) g_cnt[i] = cnt < MAXNB ? cnt : MAXNB;
}

// ---------------- fused prologue splits: x, fcnW, W0 ----------------
__device__ __forceinline__ void split_store(float4 v, __nv_bfloat16* hi,
                                            __nv_bfloat16* lo, int idx) {
    float xs[4] = {v.x, v.y, v.z, v.w};
    __nv_bfloat16 h[4], l[4];
#pragma unroll
    for (int q = 0; q < 4; q++) {
        h[q] = __float2bfloat16(xs[q]);
        l[q] = __float2bfloat16(xs[q] - __bfloat162float(h[q]));
    }
    __nv_bfloat162* hp = reinterpret_cast<__nv_bfloat162*>(hi) + idx * 2;
    __nv_bfloat162* lp = reinterpret_cast<__nv_bfloat162*>(lo) + idx * 2;
    hp[0] = __nv_bfloat162(h[0], h[1]); hp[1] = __nv_bfloat162(h[2], h[3]);
    lp[0] = __nv_bfloat162(l[0], l[1]); lp[1] = __nv_bfloat162(l[2], l[3]);
}

#define NX4 (NV * FEAT / 4)
#define NW4 (HID * FEAT / 4)

__global__ void k_prep(const float* __restrict__ x, const float* __restrict__ fcnW,
                       const float* __restrict__ W0,
                       __nv_bfloat16* __restrict__ xhi, __nv_bfloat16* __restrict__ xlo,
                       __nv_bfloat16* __restrict__ whi, __nv_bfloat16* __restrict__ wlo) {
    int idx = blockIdx.x * 256 + threadIdx.x;
    if (idx < NX4) {
        float4 v = __ldcs(reinterpret_cast<const float4*>(x) + idx);
        split_store(v, xhi, xlo, idx);
    } else if (idx < NX4 + 2 * NW4) {
        int k = idx - NX4;
        const float* S = (k < NW4) ? fcnW : W0;
        int src = (k < NW4) ? k : k - NW4;
        float4 v = __ldcs(reinterpret_cast<const float4*>(S) + src);
        split_store(v, whi, wlo, k);
    }
}

// W1 split
__global__ void k_split(const float* __restrict__ X,
                        __nv_bfloat16* __restrict__ hi,
                        __nv_bfloat16* __restrict__ lo, int n4) {
    int idx = blockIdx.x * 256 + threadIdx.x;
    if (idx >= n4) return;
    float4 v = __ldcs(reinterpret_cast<const float4*>(X) + idx);
    split_store(v, hi, lo, idx);
}

// ---------------- mma.sync bf16 GEMM, fused 3xBF16 products ----------------
#define G_ROWB   80
#define F_TILE   (128 * G_ROWB)   // 10240
#define F_STAGE  (4 * F_TILE)     // 40960 (Ah|Al|Bh|Bl)
#define F_SMEM   (2 * F_STAGE)    // 81920

__global__ __launch_bounds__(256, 2)
void k_mma_gemm(const __nv_bfloat16* __restrict__ Ah, const __nv_bfloat16* __restrict__ Al,
                const __nv_bfloat16* __restrict__ Bh, const __nv_bfloat16* __restrict__ Bl,
                const float* __restrict__ biasa, const float* __restrict__ biasb,
                float* __restrict__ Ca, float* __restrict__ Cb,
                int K, int elu_split)
{
    extern __shared__ char smem[];
    uint32_t sb = smem_to_u32(smem);
    int tid = threadIdx.x;
    int wid = tid >> 5, lane = tid & 31;
    int wm = wid >> 2, wn = wid & 3;
    int gid = lane >> 2, tk = (lane & 3) * 2;
    int bm = blockIdx.x * 128, bnw = blockIdx.y * 128;

    uint32_t a_lane = (uint32_t)(((lane & 7) + ((lane >> 3) & 1) * 8) * G_ROWB
                                 + (lane >> 4) * 16);
    uint32_t b_lane = (uint32_t)(((lane & 7) + (lane >> 4) * 8) * G_ROWB
                                 + ((lane >> 3) & 1) * 16);

    float d[4][4][4];
#pragma unroll
    for (int ma = 0; ma < 4; ma++)
#pragma unroll
        for (int na = 0; na < 4; na++)
#pragma unroll
            for (int q = 0; q < 4; q++) d[ma][na][q] = 0.f;

    int NC = K / 32;
    int lrow = tid >> 2, lq = tid & 3;
    uint32_t lso  = (uint32_t)(lrow * G_ROWB + lq * 16);
    uint32_t lso2 = (uint32_t)((lrow + 64) * G_ROWB + lq * 16);

#define ISSUE_CHUNK(c_) do {                                                        \
        int k0_ = (c_) * 32;                                                        \
        uint32_t sst_ = sb + ((c_) & 1) * F_STAGE;                                  \
        cp16(sst_ + lso,                Ah + (size_t)(bm + lrow) * K + k0_ + lq * 8);        \
        cp16(sst_ + lso2,               Ah + (size_t)(bm + lrow + 64) * K + k0_ + lq * 8);   \
        cp16(sst_ + F_TILE + lso,       Al + (size_t)(bm + lrow) * K + k0_ + lq * 8);        \
        cp16(sst_ + F_TILE + lso2,      Al + (size_t)(bm + lrow + 64) * K + k0_ + lq * 8);   \
        cp16(sst_ + 2 * F_TILE + lso,   Bh + (size_t)(bnw + lrow) * K + k0_ + lq * 8);       \
        cp16(sst_ + 2 * F_TILE + lso2,  Bh + (size_t)(bnw + lrow + 64) * K + k0_ + lq * 8);  \
        cp16(sst_ + 3 * F_TILE + lso,   Bl + (size_t)(bnw + lrow) * K + k0_ + lq * 8);       \
        cp16(sst_ + 3 * F_TILE + lso2,  Bl + (size_t)(bnw + lrow + 64) * K + k0_ + lq * 8);  \
        CP_COMMIT();                                                                \
    } while (0)

    ISSUE_CHUNK(0);

    for (int c = 0; c < NC; c++) {
        if (c + 1 < NC) { ISSUE_CHUNK(c + 1); CP_WAIT1(); }
        else { CP_WAIT0(); }
        __syncthreads();

        uint32_t st = sb + (c & 1) * F_STAGE;
        uint32_t sAh = st, sAl = st + F_TILE;
        uint32_t sBh = st + 2 * F_TILE, sBl = st + 3 * F_TILE;

#pragma unroll
        for (int kk2 = 0; kk2 < 2; kk2++) {
            uint32_t ko = (uint32_t)(kk2 * 32);
            uint32_t bh[4][2], bl[4][2];
#pragma unroll
            for (int p = 0; p < 2; p++) {
                uint32_t boff = (uint32_t)((wn * 32 + p * 16) * G_ROWB) + ko + b_lane;
                uint32_t rh[4], rl[4];
                ldsm_x4(rh, sBh + boff);
                ldsm_x4(rl, sBl + boff);
                bh[p * 2][0] = rh[0]; bh[p * 2][1] = rh[1];
                bh[p * 2 + 1][0] = rh[2]; bh[p * 2 + 1][1] = rh[3];
                bl[p * 2][0] = rl[0]; bl[p * 2][1] = rl[1];
                bl[p * 2 + 1][0] = rl[2]; bl[p * 2 + 1][1] = rl[3];
            }
#pragma unroll
            for (int ma = 0; ma < 4; ma++) {
                uint32_t aoff = (uint32_t)((wm * 64 + ma * 16) * G_ROWB) + ko + a_lane;
                uint32_t ah[4], al[4];
                ldsm_x4(ah, sAh + aoff);
                ldsm_x4(al, sAl + aoff);
#pragma unroll
                for (int na = 0; na < 4; na++) {
                    mma16816(d[ma][na], ah, bh[na]);
                    mma16816(d[ma][na], ah, bl[na]);
                    mma16816(d[ma][na], al, bh[na]);
                }
            }
        }
        __syncthreads();
    }

    // epilogue (+ fused row sum-of-squares partials for non-elu tiles)
    bool first = (blockIdx.y < (unsigned)elu_split);
    float* C = first ? Ca : Cb;
    const float* bias = first ? biasa : biasb;
    int coloff = first ? bnw : bnw - elu_split * 128;
    float rs0[4], rs1[4];
#pragma unroll
    for (int ma = 0; ma < 4; ma++) { rs0[ma] = 0.f; rs1[ma] = 0.f; }
#pragma unroll
    for (int ma = 0; ma < 4; ma++) {
        int r0 = bm + wm * 64 + ma * 16 + gid;
#pragma unroll
        for (int na = 0; na < 4; na++) {
            int col = coloff + wn * 32 + na * 8 + tk;
            float b0 = bias[col], b1 = bias[col + 1];
            float v0 = d[ma][na][0] + b0, v1 = d[ma][na][1] + b1;
            float v2 = d[ma][na][2] + b0, v3 = d[ma][na][3] + b1;
            if (first) { v0 = eluf(v0); v1 = eluf(v1); v2 = eluf(v2); v3 = eluf(v3); }
            rs0[ma] += v0 * v0 + v1 * v1;
            rs1[ma] += v2 * v2 + v3 * v3;
            *reinterpret_cast<float2*>(C + (size_t)r0 * 256 + col)       = make_float2(v0, v1);
            *reinterpret_cast<float2*>(C + (size_t)(r0 + 8) * 256 + col) = make_float2(v2, v3);
        }
    }
    if (!first) {
        float* parts = reinterpret_cast<float*>(smem);   // [4][128]
#pragma unroll
        for (int ma = 0; ma < 4; ma++) {
            float s0 = rs0[ma], s1 = rs1[ma];
            s0 += __shfl_xor_sync(0xffffffffu, s0, 1);
            s0 += __shfl_xor_sync(0xffffffffu, s0, 2);
            s1 += __shfl_xor_sync(0xffffffffu, s1, 1);
            s1 += __shfl_xor_sync(0xffffffffu, s1, 2);
            if ((lane & 3) == 0) {
                int r = wm * 64 + ma * 16 + gid;
                parts[wn * 128 + r] = s0;
                parts[wn * 128 + r + 8] = s1;
            }
        }
        __syncthreads();
        if (tid < 128) {
            float t = parts[tid] + parts[128 + tid] + parts[256 + tid] + parts[384 + tid];
            g_norm2[(size_t)(blockIdx.y - elu_split) * NV + bm + tid] = t;
        }
    }
#undef ISSUE_CHUNK
}

// ---------------- small GEMM for layer 2 (Nc=16) + fused norm partials ----------------
__global__ __launch_bounds__(256) void k_gemm_small(
    const float* __restrict__ A, const float* __restrict__ W,
    const float* __restrict__ bias, float* __restrict__ C,
    int M, int Nc, int K)
{
    __shared__ float Ws[CLS][HID];
    int tid = threadIdx.x;
    for (int idx = tid; idx < Nc * K; idx += 256)
        Ws[idx / K][idx % K] = W[idx];
    __syncthreads();
    int row = blockIdx.x * 8 + (tid >> 5);
    int lane = tid & 31;
    const float4* ap = reinterpret_cast<const float4*>(A + (size_t)row * K);
    float4 a0 = ap[lane];
    float4 a1 = ap[lane + 32];
    float accv[CLS];
    float sumsq = 0.f;
#pragma unroll
    for (int c = 0; c < CLS; c++) {
        float4 w0 = *reinterpret_cast<const float4*>(&Ws[c][lane * 4]);
        float4 w1 = *reinterpret_cast<const float4*>(&Ws[c][lane * 4 + 128]);
        float s = a0.x * w0.x + a0.y * w0.y + a0.z * w0.z + a0.w * w0.w
                + a1.x * w1.x + a1.y * w1.y + a1.z * w1.z + a1.w * w1.w;
#pragma unroll
        for (int o = 16; o; o >>= 1) s += __shfl_xor_sync(0xffffffffu, s, o);
        accv[c] = s + bias[c];
        sumsq += accv[c] * accv[c];
    }
    if (lane < CLS) C[(size_t)row * CLS + lane] = accv[lane];
    if (lane == 0) { g_norm2[row] = sumsq; g_norm2[NV + row] = 0.f; }
}

// ---------------- sparse attention: WARP PER ROW, scalar index prefetch ----------------
template<int D, bool RES, bool SPLIT>
__global__ __launch_bounds__(256, 4) void k_sparse(
    const float* __restrict__ Wh, float* __restrict__ out,
    const float* __restrict__ dc, const float* __restrict__ co,
    const float* __restrict__ sp, float coef,
    __nv_bfloat16* __restrict__ phi, __nv_bfloat16* __restrict__ plo)
{
    int i = blockIdx.x * 8 + (threadIdx.x >> 5);
    int lane = threadIdx.x & 31;

    float nsqi = g_norm2[i] + g_norm2[NV + i];
    float diag = g_diag[i];
    float dc0 = dc[0], dc1 = dc[1];
    float cm = fmaxf(co[0], fmaxf(co[1], co[2]));
    float ce0 = __expf(co[0] - cm), ce1 = __expf(co[1] - cm), ce2 = __expf(co[2] - cm);
    float cden = ce0 + ce1 + ce2;
    float s = softplusf(sp[0]);
    float c0s = s * ce0 / cden, c1s = s * ce1 / cden, c2s = s * ce2 / cden;
    int nn = g_cnt[i];
    int base = i * MAXNB;

    if constexpr (D == 256) {
        const float4* wip = reinterpret_cast<const float4*>(Wh + (size_t)i * D);
        float4 wi0 = wip[lane], wi1 = wip[lane + 32];
        float4 ac0 = make_float4(0, 0, 0, 0), ac1 = ac0;

        // prefetched indices/adj/norms for the current pair
        int j0, j1; float a0, a1, nsq0, nsq1; bool h1c;
        {
            h1c = 1 < nn;
            j0 = g_col[base]; a0 = g_adjv[base];
            int o1 = base + (h1c ? 1 : 0);
            j1 = g_col[o1]; a1 = g_adjv[o1];
            nsq0 = g_norm2[j0] + g_norm2[NV + j0];
            nsq1 = g_norm2[j1] + g_norm2[NV + j1];
        }

        for (int t = 0; t < nn; t += 2) {
            // row loads for current pair (indices already resident)
            const float4* wj0 = reinterpret_cast<const float4*>(Wh + (size_t)j0 * D);
            const float4* wj1 = reinterpret_cast<const float4*>(Wh + (size_t)j1 * D);
            float4 u0 = wj0[lane], u1 = wj0[lane + 32];
            float4 q0 = wj1[lane], q1 = wj1[lane + 32];

            // prefetch next pair's scalars while rows are in flight
            int jn0 = j0, jn1 = j1; float an0 = a0, an1 = a1, nn0 = nsq0, nn1 = nsq1;
            bool hn1 = h1c;
            int tn = t + 2;
            bool more = tn < nn;
            if (more) {
                hn1 = tn + 1 < nn;
                int o0 = base + tn;
                int o1 = base + (hn1 ? tn + 1 : tn);
                jn0 = g_col[o0]; an0 = g_adjv[o0];
                jn1 = g_col[o1]; an1 = g_adjv[o1];
                nn0 = g_norm2[jn0] + g_norm2[NV + jn0];
                nn1 = g_norm2[jn1] + g_norm2[NV + jn1];
            }

            float p0 = wi0.x * u0.x + wi0.y * u0.y + wi0.z * u0.z + wi0.w * u0.w
                     + wi1.x * u1.x + wi1.y * u1.y + wi1.z * u1.z + wi1.w * u1.w;
            float p1 = wi0.x * q0.x + wi0.y * q0.y + wi0.z * q0.z + wi0.w * q0.w
                     + wi1.x * q1.x + wi1.y * q1.y + wi1.z * q1.z + wi1.w * q1.w;
#pragma unroll
            for (int o = 16; o; o >>= 1) {
                p0 += __shfl_xor_sync(0xffffffffu, p0, o);
                p1 += __shfl_xor_sync(0xffffffffu, p1, o);
            }
            float e0 = p0 * rsqrtf(fmaxf(nsqi * nsq0, 1e-18f));
            float e1 = p1 * rsqrtf(fmaxf(nsqi * nsq1, 1e-18f));
            float sc0 = softplus_fast(dc0 * (__fdividef(diag, a0) - 1.f) + dc1);
            float sc1 = softplus_fast(dc0 * (__fdividef(diag, a1) - 1.f) + dc1);
            float att0 = (j0 == i) ? 0.f : e0 * a0 * sc0;
            float att1 = (j1 == i || !h1c) ? 0.f : e1 * a1 * sc1;
            float wg0 = c0s * fmaxf(att0, 0.f) + c1s * fminf(att0, 0.f);
            float wg1 = c0s * fmaxf(att1, 0.f) + c1s * fminf(att1, 0.f);
            ac0.x += wg0 * u0.x + wg1 * q0.x; ac0.y += wg0 * u0.y + wg1 * q0.y;
            ac0.z += wg0 * u0.z + wg1 * q0.z; ac0.w += wg0 * u0.w + wg1 * q0.w;
            ac1.x += wg0 * u1.x + wg1 * q1.x; ac1.y += wg0 * u1.y + wg1 * q1.y;
            ac1.z += wg0 * u1.z + wg1 * q1.z; ac1.w += wg0 * u1.w + wg1 * q1.w;

            j0 = jn0; j1 = jn1; a0 = an0; a1 = an1;
            nsq0 = nn0; nsq1 = nn1; h1c = hn1;
        }

        float o0[4] = {ac0.x + c2s * wi0.x, ac0.y + c2s * wi0.y,
                       ac0.z + c2s * wi0.z, ac0.w + c2s * wi0.w};
        float o1[4] = {ac1.x + c2s * wi1.x, ac1.y + c2s * wi1.y,
                       ac1.z + c2s * wi1.z, ac1.w + c2s * wi1.w};
        size_t rbase = (size_t)i * D + lane * 4;
        if (RES) {
            float4 P0 = *reinterpret_cast<float4*>(out + rbase);
            float4 P1 = *reinterpret_cast<float4*>(out + rbase + 128);
            float n0[4] = {P0.x + coef * eluf(o0[0]), P0.y + coef * eluf(o0[1]),
                           P0.z + coef * eluf(o0[2]), P0.w + coef * eluf(o0[3])};
            float n1[4] = {P1.x + coef * eluf(o1[0]), P1.y + coef * eluf(o1[1]),
                           P1.z + coef * eluf(o1[2]), P1.w + coef * eluf(o1[3])};
            *reinterpret_cast<float4*>(out + rbase)       = make_float4(n0[0], n0[1], n0[2], n0[3]);
            *reinterpret_cast<float4*>(out + rbase + 128) = make_float4(n1[0], n1[1], n1[2], n1[3]);
            if (SPLIT) {
#pragma unroll
                for (int g = 0; g < 2; g++) {
                    const float* nv = g ? n1 : n0;
                    size_t off = rbase + g * 128;
                    __nv_bfloat16 h[4], l[4];
#pragma unroll
                    for (int q = 0; q < 4; q++) {
                        h[q] = __float2bfloat16(nv[q]);
                        l[q] = __float2bfloat16(nv[q] - __bfloat162float(h[q]));
                    }
                    __nv_bfloat162* hp = reinterpret_cast<__nv_bfloat162*>(phi + off);
                    __nv_bfloat162* lp = reinterpret_cast<__nv_bfloat162*>(plo + off);
                    hp[0] = __nv_bfloat162(h[0], h[1]); hp[1] = __nv_bfloat162(h[2], h[3]);
                    lp[0] = __nv_bfloat162(l[0], l[1]); lp[1] = __nv_bfloat162(l[2], l[3]);
                }
            }
        } else {
            *reinterpret_cast<float4*>(out + rbase)       = make_float4(o0[0], o0[1], o0[2], o0[3]);
            *reinterpret_cast<float4*>(out + rbase + 128) = make_float4(o1[0], o1[1], o1[2], o1[3]);
        }
    } else {
        // D == 16: lanes 0-15 own one dim each
        float wi = (lane < D) ? Wh[(size_t)i * D + lane] : 0.f;
        float ac = 0.f;
        for (int t = 0; t < nn; t++) {
            int j = g_col[base + t];
            float a = g_adjv[base + t];
            float v = (lane < D) ? Wh[(size_t)j * D + lane] : 0.f;
            float p = wi * v;
#pragma unroll
            for (int o = 16; o; o >>= 1) p += __shfl_xor_sync(0xffffffffu, p, o);
            float nsq = g_norm2[j] + g_norm2[NV + j];
            float e = p * rsqrtf(fmaxf(nsqi * nsq, 1e-18f));
            float sc = softplus_fast(dc0 * (__fdividef(diag, a) - 1.f) + dc1);
            float att = (j != i) ? e * a * sc : 0.f;
            float wgt = c0s * fmaxf(att, 0.f) + c1s * fminf(att, 0.f);
            ac += wgt * v;
        }
        if (lane < D) {
            float outv = ac + c2s * wi;
            out[(size_t)i * D + lane] = outv;
        }
    }
}

// ---------------- head: log_softmax + softmax + top2 ----------------
__global__ void k_head(const float* __restrict__ C, float* __restrict__ logp,
                       float* __restrict__ pred) {
    int g = threadIdx.x >> 4;
    int l = threadIdx.x & 15;
    int row = blockIdx.x * 16 + g;
    float x = C[row * CLS + l];
    float m = x;
#pragma unroll
    for (int o = 8; o; o >>= 1) m = fmaxf(m, __shfl_xor_sync(0xffffffffu, m, o, 16));
    float ex = expf(x - m);
    float se = ex;
#pragma unroll
    for (int o = 8; o; o >>= 1) se += __shfl_xor_sync(0xffffffffu, se, o, 16);
    float lse = logf(se);
    logp[row * CLS + l] = x - m - lse;
    float pr = ex / se;
    pred[row * CLS + l] = pr;
    int laneid = threadIdx.x & 31;
    int segbase = laneid & 16;
    float m1 = -1.f, m2 = -1.f;
#pragma unroll
    for (int k = 0; k < 16; k++) {
        float v = __shfl_sync(0xffffffffu, pr, segbase + k);
        if (v > m1) { m2 = m1; m1 = v; }
        else if (v > m2) m2 = v;
    }
    if (l == 0) g_t2[row] = m1 + m2;
}

// ---------------- deterministic calib reduction ----------------
__global__ void k_calib(float* __restrict__ out_calib) {
    __shared__ float sh[256];
    float s = 0.f;
    for (int i = threadIdx.x; i < NV; i += 256) s += g_t2[i];
    sh[threadIdx.x] = s;
    __syncthreads();
    for (int o = 128; o; o >>= 1) {
        if (threadIdx.x < o) sh[threadIdx.x] += sh[threadIdx.x + o];
        __syncthreads();
    }
    if (threadIdx.x == 0) out_calib[0] = sh[0] / (float)NV;
}

// ---------------- launcher ----------------
extern "C" void kernel_launch(void* const* d_in, const int* in_sizes, int n_in,
                              void* d_out, int out_size) {
    const float* x    = (const float*)d_in[0];
    const float* adj  = (const float*)d_in[1];
    const float* fcnW = (const float*)d_in[2];
    const float* fcnb = (const float*)d_in[3];
    const float* W0   = (const float*)d_in[4];
    const float* b0   = (const float*)d_in[5];
    const float* dc0  = (const float*)d_in[6];
    const float* c0   = (const float*)d_in[7];
    const float* s0   = (const float*)d_in[8];
    const float* W1   = (const float*)d_in[9];
    const float* b1   = (const float*)d_in[10];
    const float* dc1  = (const float*)d_in[11];
    const float* c1   = (const float*)d_in[12];
    const float* s1   = (const float*)d_in[13];
    const float* W2   = (const float*)d_in[14];
    const float* b2   = (const float*)d_in[15];
    const float* dc2  = (const float*)d_in[16];
    const float* c2   = (const float*)d_in[17];
    const float* s2   = (const float*)d_in[18];

    float* out       = (float*)d_out;
    float* out_logp  = out;
    float* out_calib = out + NV * CLS;
    float* out_pred  = out + NV * CLS + 1;

    float *pP, *pA, *pC16, *pO16;
    cudaGetSymbolAddress((void**)&pP,   g_P);
    cudaGetSymbolAddress((void**)&pA,   g_A);
    cudaGetSymbolAddress((void**)&pC16, g_C16);
    cudaGetSymbolAddress((void**)&pO16, g_O16);
    __nv_bfloat16 *pxh, *pxl, *pph, *ppl, *pwh, *pwl;
    cudaGetSymbolAddress((void**)&pxh, g_xhi);
    cudaGetSymbolAddress((void**)&pxl, g_xlo);
    cudaGetSymbolAddress((void**)&pph, g_phi);
    cudaGetSymbolAddress((void**)&ppl, g_plo);
    cudaGetSymbolAddress((void**)&pwh, g_whi);
    cudaGetSymbolAddress((void**)&pwl, g_wlo);

    cudaFuncSetAttribute(k_mma_gemm, cudaFuncAttributeMaxDynamicSharedMemorySize, F_SMEM);

    // 0: fused splits (x, fcnW, W0)
    k_prep<<<(NX4 + 2 * NW4 + 255) / 256, 256>>>(x, fcnW, W0, pxh, pxl, pwh, pwl);

    // 1: merged GEMM: prev = elu(x@fcnW^T+fcnb)  AND  Wh0 = x@W0^T+b0 (+norm partials)
    k_mma_gemm<<<dim3(NV / 128, 4), 256, F_SMEM>>>(pxh, pxl, pwh, pwl,
                                                   fcnb, b0, pP, pA, FEAT, 2);

    // 2: CSR from adjacency (also extracts diag)
    k_build_csr<<<NV, 256>>>(adj);

    // 3 (PROFILED): layer 0 sparse (warp-per-row, scalar prefetch)
    k_sparse<HID, true, true><<<NV / 8, 256>>>(pA, pP, dc0, c0, s0, 1.0f, pph, ppl);

    // ---- layer 1 (input prev) ----
    k_split<<<(HID * HID / 4 + 255) / 256, 256>>>(W1, pwh, pwl, HID * HID / 4);
    k_mma_gemm<<<dim3(NV / 128, 2), 256, F_SMEM>>>(pph, ppl, pwh, pwl,
                                                   b1, b1, pA, pA, HID, 0);
    float decay = (float)log(0.9 / 27.0 + 1.0);
    k_sparse<HID, true, false><<<NV / 8, 256>>>(pA, pP, dc1, c1, s1, decay, pph, ppl);

    // ---- layer 2 (input prev, D=16; norm fused into small GEMM) ----
    k_gemm_small<<<NV / 8, 256>>>(pP, W2, b2, pC16, NV, CLS, HID);
    k_sparse<CLS, false, false><<<NV / 8, 256>>>(pC16, pO16, dc2, c2, s2, 0.0f, pph, ppl);

    // ---- head ----
    k_head<<<NV / 16, 256>>>(pO16, out_logp, out_pred);
    k_calib<<<1, 256>>>(out_calib);
}

// round 16
// speedup vs baseline: 1.1655x; 1.0897x over previous
#include <cuda_runtime.h>
#include <cuda_bf16.h>
#include <math.h>
#include <stdint.h>

#define NV    8192
#define FEAT  1024
#define HID   256
#define CLS   16
#define MAXNB 192

// ---------------- device scratch (no allocations allowed) ----------------
__device__ int   g_col[NV * MAXNB];
__device__ float g_adjv[NV * MAXNB];
__device__ int   g_cnt[NV];
__device__ float g_diag[NV];
__device__ float g_P[NV * HID];     // residual stream
__device__ float g_A[NV * HID];     // Wh
__device__ float g_C16[NV * CLS];
__device__ float g_O16[NV * CLS];
__device__ float g_norm2[2 * NV];   // per-column-tile partial sum-of-squares
__device__ float g_t2[NV];
// bf16 hi/lo splits for tensor-core GEMM (W1 parked after fcnW|W0)
__device__ __nv_bfloat16 g_xhi[NV * FEAT];
__device__ __nv_bfloat16 g_xlo[NV * FEAT];
__device__ __nv_bfloat16 g_phi[NV * HID];
__device__ __nv_bfloat16 g_plo[NV * HID];
__device__ __nv_bfloat16 g_whi[2 * HID * FEAT + HID * HID];
__device__ __nv_bfloat16 g_wlo[2 * HID * FEAT + HID * HID];

__device__ __forceinline__ float softplusf(float x) {        // accurate
    return x > 20.f ? x : log1pf(expf(x));
}
__device__ __forceinline__ float softplus_fast(float x) {    // MUFU-based
    return x > 20.f ? x : __logf(1.f + __expf(x));
}
__device__ __forceinline__ float eluf(float x) {
    return x > 0.f ? x : expm1f(x);
}
__device__ __forceinline__ uint32_t smem_to_u32(const void* smem_ptr) {
    uint32_t addr;
    asm("{ .reg .u64 tmp; cvta.to.shared.u64 tmp, %1; cvt.u32.u64 %0, tmp; }"
        : "=r"(addr) : "l"(smem_ptr));
    return addr;
}
__device__ __forceinline__ void cp16(uint32_t dst, const void* src) {
    asm volatile("cp.async.cg.shared.global [%0], [%1], 16;"
                 :: "r"(dst), "l"(src) : "memory");
}
#define CP_COMMIT() asm volatile("cp.async.commit_group;" ::: "memory")
#define CP_WAIT0()  asm volatile("cp.async.wait_group 0;" ::: "memory")
#define CP_WAIT1()  asm volatile("cp.async.wait_group 1;" ::: "memory")

__device__ __forceinline__ void mma16816(float* d, const uint32_t* a, const uint32_t* b) {
    asm volatile(
        "mma.sync.aligned.m16n8k16.row.col.f32.bf16.bf16.f32 "
        "{%0,%1,%2,%3}, {%4,%5,%6,%7}, {%8,%9}, {%0,%1,%2,%3};"
        : "+f"(d[0]), "+f"(d[1]), "+f"(d[2]), "+f"(d[3])
        : "r"(a[0]), "r"(a[1]), "r"(a[2]), "r"(a[3]), "r"(b[0]), "r"(b[1]));
}
__device__ __forceinline__ void ldsm_x4(uint32_t* r, uint32_t addr) {
    asm volatile("ldmatrix.sync.aligned.m8n8.x4.shared.b16 {%0,%1,%2,%3}, [%4];"
        : "=r"(r[0]), "=r"(r[1]), "=r"(r[2]), "=r"(r[3]) : "r"(addr));
}

// ---------------- CSR build from dense adjacency (OR-tree fast scan) ----------------
__device__ __forceinline__ void csr_extract(int i, int cbase, uint4 u, int* cnt) {
    uint32_t v0 = u.x, v1 = u.y, v2 = u.z, v3 = u.w;
    if (v0) { int p = atomicAdd(cnt, 1); if (p < MAXNB) { g_col[i * MAXNB + p] = cbase + 0; g_adjv[i * MAXNB + p] = __uint_as_float(v0); } }
    if (v1) { int p = atomicAdd(cnt, 1); if (p < MAXNB) { g_col[i * MAXNB + p] = cbase + 1; g_adjv[i * MAXNB + p] = __uint_as_float(v1); } }
    if (v2) { int p = atomicAdd(cnt, 1); if (p < MAXNB) { g_col[i * MAXNB + p] = cbase + 2; g_adjv[i * MAXNB + p] = __uint_as_float(v2); } }
    if (v3) { int p = atomicAdd(cnt, 1); if (p < MAXNB) { g_col[i * MAXNB + p] = cbase + 3; g_adjv[i * MAXNB + p] = __uint_as_float(v3); } }
}

__global__ __launch_bounds__(256) void k_build_csr(const float* __restrict__ adj) {
    int i = blockIdx.x;
    __shared__ int cnt;
    if (threadIdx.x == 0) {
        cnt = 0;
        g_diag[i] = adj[(size_t)i * NV + i];
    }
    __syncthreads();
    const uint4* row = reinterpret_cast<const uint4*>(adj + (size_t)i * NV);
    int tid = threadIdx.x;
#pragma unroll
    for (int it = 0; it < 2; it++) {
        int c0 = tid + (it * 4 + 0) * 256;
        int c1 = tid + (it * 4 + 1) * 256;
        int c2 = tid + (it * 4 + 2) * 256;
        int c3 = tid + (it * 4 + 3) * 256;
        uint4 u0 = __ldcs(&row[c0]);
        uint4 u1 = __ldcs(&row[c1]);
        uint4 u2 = __ldcs(&row[c2]);
        uint4 u3 = __ldcs(&row[c3]);
        uint32_t m = (u0.x | u0.y | u0.z) | (u0.w | u1.x | u1.y) |
                     (u1.z | u1.w | u2.x) | (u2.y | u2.z | u2.w) |
                     (u3.x | u3.y | u3.z) | u3.w;
        if (m) {
            csr_extract(i, c0 * 4, u0, &cnt);
            csr_extract(i, c1 * 4, u1, &cnt);
            csr_extract(i, c2 * 4, u2, &cnt);
            csr_extract(i, c3 * 4, u3, &cnt);
        }
    }
    __syncthreads();
    if (threadIdx.x == 0) g_cnt[i] = cnt < MAXNB ? cnt : MAXNB;
}

// ---------------- fused prologue splits: x, fcnW, W0, W1 ----------------
__device__ __forceinline__ void split_store(float4 v, __nv_bfloat16* hi,
                                            __nv_bfloat16* lo, int idx) {
    float xs[4] = {v.x, v.y, v.z, v.w};
    __nv_bfloat16 h[4], l[4];
#pragma unroll
    for (int q = 0; q < 4; q++) {
        h[q] = __float2bfloat16(xs[q]);
        l[q] = __float2bfloat16(xs[q] - __bfloat162float(h[q]));
    }
    __nv_bfloat162* hp = reinterpret_cast<__nv_bfloat162*>(hi) + idx * 2;
    __nv_bfloat162* lp = reinterpret_cast<__nv_bfloat162*>(lo) + idx * 2;
    hp[0] = __nv_bfloat162(h[0], h[1]); hp[1] = __nv_bfloat162(h[2], h[3]);
    lp[0] = __nv_bfloat162(l[0], l[1]); lp[1] = __nv_bfloat162(l[2], l[3]);
}

#define NX4  (NV * FEAT / 4)
#define NW4  (HID * FEAT / 4)
#define NW14 (HID * HID / 4)
#define W1_OFF (2 * HID * FEAT)

__global__ void k_prep(const float* __restrict__ x, const float* __restrict__ fcnW,
                       const float* __restrict__ W0, const float* __restrict__ W1,
                       __nv_bfloat16* __restrict__ xhi, __nv_bfloat16* __restrict__ xlo,
                       __nv_bfloat16* __restrict__ whi, __nv_bfloat16* __restrict__ wlo) {
    int idx = blockIdx.x * 256 + threadIdx.x;
    if (idx < NX4) {
        float4 v = __ldcs(reinterpret_cast<const float4*>(x) + idx);
        split_store(v, xhi, xlo, idx);
    } else if (idx < NX4 + 2 * NW4) {
        int k = idx - NX4;
        const float* S = (k < NW4) ? fcnW : W0;
        int src = (k < NW4) ? k : k - NW4;
        float4 v = __ldcs(reinterpret_cast<const float4*>(S) + src);
        split_store(v, whi, wlo, k);
    } else if (idx < NX4 + 2 * NW4 + NW14) {
        int k = idx - NX4 - 2 * NW4;
        float4 v = __ldcs(reinterpret_cast<const float4*>(W1) + k);
        split_store(v, whi, wlo, W1_OFF / 4 + k);
    }
}

// ---------------- mma.sync bf16 GEMM, fused 3xBF16 products ----------------
#define G_ROWB   80
#define F_TILE   (128 * G_ROWB)   // 10240
#define F_STAGE  (4 * F_TILE)     // 40960 (Ah|Al|Bh|Bl)
#define F_SMEM   (2 * F_STAGE)    // 81920

__global__ __launch_bounds__(256, 2)
void k_mma_gemm(const __nv_bfloat16* __restrict__ Ah, const __nv_bfloat16* __restrict__ Al,
                const __nv_bfloat16* __restrict__ Bh, const __nv_bfloat16* __restrict__ Bl,
                const float* __restrict__ biasa, const float* __restrict__ biasb,
                float* __restrict__ Ca, float* __restrict__ Cb,
                int K, int elu_split)
{
    extern __shared__ char smem[];
    uint32_t sb = smem_to_u32(smem);
    int tid = threadIdx.x;
    int wid = tid >> 5, lane = tid & 31;
    int wm = wid >> 2, wn = wid & 3;
    int gid = lane >> 2, tk = (lane & 3) * 2;
    int bm = blockIdx.x * 128, bnw = blockIdx.y * 128;

    uint32_t a_lane = (uint32_t)(((lane & 7) + ((lane >> 3) & 1) * 8) * G_ROWB
                                 + (lane >> 4) * 16);
    uint32_t b_lane = (uint32_t)(((lane & 7) + (lane >> 4) * 8) * G_ROWB
                                 + ((lane >> 3) & 1) * 16);

    float d[4][4][4];
#pragma unroll
    for (int ma = 0; ma < 4; ma++)
#pragma unroll
        for (int na = 0; na < 4; na++)
#pragma unroll
            for (int q = 0; q < 4; q++) d[ma][na][q] = 0.f;

    int NC = K / 32;
    int lrow = tid >> 2, lq = tid & 3;
    uint32_t lso  = (uint32_t)(lrow * G_ROWB + lq * 16);
    uint32_t lso2 = (uint32_t)((lrow + 64) * G_ROWB + lq * 16);

#define ISSUE_CHUNK(c_) do {                                                        \
        int k0_ = (c_) * 32;                                                        \
        uint32_t sst_ = sb + ((c_) & 1) * F_STAGE;                                  \
        cp16(sst_ + lso,                Ah + (size_t)(bm + lrow) * K + k0_ + lq * 8);        \
        cp16(sst_ + lso2,               Ah + (size_t)(bm + lrow + 64) * K + k0_ + lq * 8);   \
        cp16(sst_ + F_TILE + lso,       Al + (size_t)(bm + lrow) * K + k0_ + lq * 8);        \
        cp16(sst_ + F_TILE + lso2,      Al + (size_t)(bm + lrow + 64) * K + k0_ + lq * 8);   \
        cp16(sst_ + 2 * F_TILE + lso,   Bh + (size_t)(bnw + lrow) * K + k0_ + lq * 8);       \
        cp16(sst_ + 2 * F_TILE + lso2,  Bh + (size_t)(bnw + lrow + 64) * K + k0_ + lq * 8);  \
        cp16(sst_ + 3 * F_TILE + lso,   Bl + (size_t)(bnw + lrow) * K + k0_ + lq * 8);       \
        cp16(sst_ + 3 * F_TILE + lso2,  Bl + (size_t)(bnw + lrow + 64) * K + k0_ + lq * 8);  \
        CP_COMMIT();                                                                \
    } while (0)

    ISSUE_CHUNK(0);

    for (int c = 0; c < NC; c++) {
        if (c + 1 < NC) { ISSUE_CHUNK(c + 1); CP_WAIT1(); }
        else { CP_WAIT0(); }
        __syncthreads();

        uint32_t st = sb + (c & 1) * F_STAGE;
        uint32_t sAh = st, sAl = st + F_TILE;
        uint32_t sBh = st + 2 * F_TILE, sBl = st + 3 * F_TILE;

#pragma unroll
        for (int kk2 = 0; kk2 < 2; kk2++) {
            uint32_t ko = (uint32_t)(kk2 * 32);
            uint32_t bh[4][2], bl[4][2];
#pragma unroll
            for (int p = 0; p < 2; p++) {
                uint32_t boff = (uint32_t)((wn * 32 + p * 16) * G_ROWB) + ko + b_lane;
                uint32_t rh[4], rl[4];
                ldsm_x4(rh, sBh + boff);
                ldsm_x4(rl, sBl + boff);
                bh[p * 2][0] = rh[0]; bh[p * 2][1] = rh[1];
                bh[p * 2 + 1][0] = rh[2]; bh[p * 2 + 1][1] = rh[3];
                bl[p * 2][0] = rl[0]; bl[p * 2][1] = rl[1];
                bl[p * 2 + 1][0] = rl[2]; bl[p * 2 + 1][1] = rl[3];
            }
#pragma unroll
            for (int ma = 0; ma < 4; ma++) {
                uint32_t aoff = (uint32_t)((wm * 64 + ma * 16) * G_ROWB) + ko + a_lane;
                uint32_t ah[4], al[4];
                ldsm_x4(ah, sAh + aoff);
                ldsm_x4(al, sAl + aoff);
#pragma unroll
                for (int na = 0; na < 4; na++) {
                    mma16816(d[ma][na], ah, bh[na]);
                    mma16816(d[ma][na], ah, bl[na]);
                    mma16816(d[ma][na], al, bh[na]);
                }
            }
        }
        __syncthreads();
    }

    // epilogue (+ fused row sum-of-squares partials for non-elu tiles)
    bool first = (blockIdx.y < (unsigned)elu_split);
    float* C = first ? Ca : Cb;
    const float* bias = first ? biasa : biasb;
    int coloff = first ? bnw : bnw - elu_split * 128;
    float rs0[4], rs1[4];
#pragma unroll
    for (int ma = 0; ma < 4; ma++) { rs0[ma] = 0.f; rs1[ma] = 0.f; }
#pragma unroll
    for (int ma = 0; ma < 4; ma++) {
        int r0 = bm + wm * 64 + ma * 16 + gid;
#pragma unroll
        for (int na = 0; na < 4; na++) {
            int col = coloff + wn * 32 + na * 8 + tk;
            float b0 = bias[col], b1 = bias[col + 1];
            float v0 = d[ma][na][0] + b0, v1 = d[ma][na][1] + b1;
            float v2 = d[ma][na][2] + b0, v3 = d[ma][na][3] + b1;
            if (first) { v0 = eluf(v0); v1 = eluf(v1); v2 = eluf(v2); v3 = eluf(v3); }
            rs0[ma] += v0 * v0 + v1 * v1;
            rs1[ma] += v2 * v2 + v3 * v3;
            *reinterpret_cast<float2*>(C + (size_t)r0 * 256 + col)       = make_float2(v0, v1);
            *reinterpret_cast<float2*>(C + (size_t)(r0 + 8) * 256 + col) = make_float2(v2, v3);
        }
    }
    if (!first) {
        float* parts = reinterpret_cast<float*>(smem);   // [4][128]
#pragma unroll
        for (int ma = 0; ma < 4; ma++) {
            float s0 = rs0[ma], s1 = rs1[ma];
            s0 += __shfl_xor_sync(0xffffffffu, s0, 1);
            s0 += __shfl_xor_sync(0xffffffffu, s0, 2);
            s1 += __shfl_xor_sync(0xffffffffu, s1, 1);
            s1 += __shfl_xor_sync(0xffffffffu, s1, 2);
            if ((lane & 3) == 0) {
                int r = wm * 64 + ma * 16 + gid;
                parts[wn * 128 + r] = s0;
                parts[wn * 128 + r + 8] = s1;
            }
        }
        __syncthreads();
        if (tid < 128) {
            float t = parts[tid] + parts[128 + tid] + parts[256 + tid] + parts[384 + tid];
            g_norm2[(size_t)(blockIdx.y - elu_split) * NV + bm + tid] = t;
        }
    }
#undef ISSUE_CHUNK
}

// ---------------- small GEMM for layer 2 (Nc=16) + fused norm partials ----------------
__global__ __launch_bounds__(256) void k_gemm_small(
    const float* __restrict__ A, const float* __restrict__ W,
    const float* __restrict__ bias, float* __restrict__ C,
    int M, int Nc, int K)
{
    __shared__ float Ws[CLS][HID];
    int tid = threadIdx.x;
    for (int idx = tid; idx < Nc * K; idx += 256)
        Ws[idx / K][idx % K] = W[idx];
    __syncthreads();
    int row = blockIdx.x * 8 + (tid >> 5);
    int lane = tid & 31;
    const float4* ap = reinterpret_cast<const float4*>(A + (size_t)row * K);
    float4 a0 = ap[lane];
    float4 a1 = ap[lane + 32];
    float accv[CLS];
    float sumsq = 0.f;
#pragma unroll
    for (int c = 0; c < CLS; c++) {
        float4 w0 = *reinterpret_cast<const float4*>(&Ws[c][lane * 4]);
        float4 w1 = *reinterpret_cast<const float4*>(&Ws[c][lane * 4 + 128]);
        float s = a0.x * w0.x + a0.y * w0.y + a0.z * w0.z + a0.w * w0.w
                + a1.x * w1.x + a1.y * w1.y + a1.z * w1.z + a1.w * w1.w;
#pragma unroll
        for (int o = 16; o; o >>= 1) s += __shfl_xor_sync(0xffffffffu, s, o);
        accv[c] = s + bias[c];
        sumsq += accv[c] * accv[c];
    }
    if (lane < CLS) C[(size_t)row * CLS + lane] = accv[lane];
    if (lane == 0) { g_norm2[row] = sumsq; g_norm2[NV + row] = 0.f; }
}

// ---------------- sparse attention + aggregation: WARP PER ROW (R13) ----------------
template<int D, bool RES, bool SPLIT>
__global__ __launch_bounds__(256) void k_sparse(
    const float* __restrict__ Wh, float* __restrict__ out,
    const float* __restrict__ dc, const float* __restrict__ co,
    const float* __restrict__ sp, float coef,
    __nv_bfloat16* __restrict__ phi, __nv_bfloat16* __restrict__ plo)
{
    int i = blockIdx.x * 8 + (threadIdx.x >> 5);
    int lane = threadIdx.x & 31;

    float nsqi = g_norm2[i] + g_norm2[NV + i];
    float diag = g_diag[i];
    float dc0 = dc[0], dc1 = dc[1];
    float cm = fmaxf(co[0], fmaxf(co[1], co[2]));
    float ce0 = __expf(co[0] - cm), ce1 = __expf(co[1] - cm), ce2 = __expf(co[2] - cm);
    float cden = ce0 + ce1 + ce2;
    float s = softplusf(sp[0]);
    float c0s = s * ce0 / cden, c1s = s * ce1 / cden, c2s = s * ce2 / cden;
    int nn = g_cnt[i];
    int base = i * MAXNB;

    if constexpr (D == 256) {
        const float4* wip = reinterpret_cast<const float4*>(Wh + (size_t)i * D);
        float4 wi0 = wip[lane], wi1 = wip[lane + 32];
        float4 ac0 = make_float4(0, 0, 0, 0), ac1 = ac0;
        for (int t = 0; t < nn; t += 2) {
            int t1 = t + 1;
            bool h1 = t1 < nn;
            int o0 = base + t;
            int o1 = base + (h1 ? t1 : t);
            int j0 = g_col[o0]; float a0 = g_adjv[o0];
            int j1 = g_col[o1]; float a1 = g_adjv[o1];
            const float4* wj0 = reinterpret_cast<const float4*>(Wh + (size_t)j0 * D);
            const float4* wj1 = reinterpret_cast<const float4*>(Wh + (size_t)j1 * D);
            float4 u0 = wj0[lane], u1 = wj0[lane + 32];
            float4 q0 = wj1[lane], q1 = wj1[lane + 32];
            float p0 = wi0.x * u0.x + wi0.y * u0.y + wi0.z * u0.z + wi0.w * u0.w
                     + wi1.x * u1.x + wi1.y * u1.y + wi1.z * u1.z + wi1.w * u1.w;
            float p1 = wi0.x * q0.x + wi0.y * q0.y + wi0.z * q0.z + wi0.w * q0.w
                     + wi1.x * q1.x + wi1.y * q1.y + wi1.z * q1.z + wi1.w * q1.w;
#pragma unroll
            for (int o = 16; o; o >>= 1) {
                p0 += __shfl_xor_sync(0xffffffffu, p0, o);
                p1 += __shfl_xor_sync(0xffffffffu, p1, o);
            }
            float nsq0 = g_norm2[j0] + g_norm2[NV + j0];
            float nsq1 = g_norm2[j1] + g_norm2[NV + j1];
            float e0 = p0 * rsqrtf(fmaxf(nsqi * nsq0, 1e-18f));
            float e1 = p1 * rsqrtf(fmaxf(nsqi * nsq1, 1e-18f));
            float sc0 = softplus_fast(dc0 * (__fdividef(diag, a0) - 1.f) + dc1);
            float sc1 = softplus_fast(dc0 * (__fdividef(diag, a1) - 1.f) + dc1);
            float att0 = (j0 == i) ? 0.f : e0 * a0 * sc0;
            float att1 = (j1 == i || !h1) ? 0.f : e1 * a1 * sc1;
            float wg0 = c0s * fmaxf(att0, 0.f) + c1s * fminf(att0, 0.f);
            float wg1 = c0s * fmaxf(att1, 0.f) + c1s * fminf(att1, 0.f);
            ac0.x += wg0 * u0.x + wg1 * q0.x; ac0.y += wg0 * u0.y + wg1 * q0.y;
            ac0.z += wg0 * u0.z + wg1 * q0.z; ac0.w += wg0 * u0.w + wg1 * q0.w;
            ac1.x += wg0 * u1.x + wg1 * q1.x; ac1.y += wg0 * u1.y + wg1 * q1.y;
            ac1.z += wg0 * u1.z + wg1 * q1.z; ac1.w += wg0 * u1.w + wg1 * q1.w;
        }
        float o0[4] = {ac0.x + c2s * wi0.x, ac0.y + c2s * wi0.y,
                       ac0.z + c2s * wi0.z, ac0.w + c2s * wi0.w};
        float o1[4] = {ac1.x + c2s * wi1.x, ac1.y + c2s * wi1.y,
                       ac1.z + c2s * wi1.z, ac1.w + c2s * wi1.w};
        size_t rbase = (size_t)i * D + lane * 4;
        if (RES) {
            float4 P0 = *reinterpret_cast<float4*>(out + rbase);
            float4 P1 = *reinterpret_cast<float4*>(out + rbase + 128);
            float n0[4] = {P0.x + coef * eluf(o0[0]), P0.y + coef * eluf(o0[1]),
                           P0.z + coef * eluf(o0[2]), P0.w + coef * eluf(o0[3])};
            float n1[4] = {P1.x + coef * eluf(o1[0]), P1.y + coef * eluf(o1[1]),
                           P1.z + coef * eluf(o1[2]), P1.w + coef * eluf(o1[3])};
            *reinterpret_cast<float4*>(out + rbase)       = make_float4(n0[0], n0[1], n0[2], n0[3]);
            *reinterpret_cast<float4*>(out + rbase + 128) = make_float4(n1[0], n1[1], n1[2], n1[3]);
            if (SPLIT) {
#pragma unroll
                for (int g = 0; g < 2; g++) {
                    const float* nv = g ? n1 : n0;
                    size_t off = rbase + g * 128;
                    __nv_bfloat16 h[4], l[4];
#pragma unroll
                    for (int q = 0; q < 4; q++) {
                        h[q] = __float2bfloat16(nv[q]);
                        l[q] = __float2bfloat16(nv[q] - __bfloat162float(h[q]));
                    }
                    __nv_bfloat162* hp = reinterpret_cast<__nv_bfloat162*>(phi + off);
                    __nv_bfloat162* lp = reinterpret_cast<__nv_bfloat162*>(plo + off);
                    hp[0] = __nv_bfloat162(h[0], h[1]); hp[1] = __nv_bfloat162(h[2], h[3]);
                    lp[0] = __nv_bfloat162(l[0], l[1]); lp[1] = __nv_bfloat162(l[2], l[3]);
                }
            }
        } else {
            *reinterpret_cast<float4*>(out + rbase)       = make_float4(o0[0], o0[1], o0[2], o0[3]);
            *reinterpret_cast<float4*>(out + rbase + 128) = make_float4(o1[0], o1[1], o1[2], o1[3]);
        }
    } else {
        // D == 16: lanes 0-15 own one dim each
        float wi = (lane < D) ? Wh[(size_t)i * D + lane] : 0.f;
        float ac = 0.f;
        for (int t = 0; t < nn; t++) {
            int j = g_col[base + t];
            float a = g_adjv[base + t];
            float v = (lane < D) ? Wh[(size_t)j * D + lane] : 0.f;
            float p = wi * v;
#pragma unroll
            for (int o = 16; o; o >>= 1) p += __shfl_xor_sync(0xffffffffu, p, o);
            float nsq = g_norm2[j] + g_norm2[NV + j];
            float e = p * rsqrtf(fmaxf(nsqi * nsq, 1e-18f));
            float sc = softplus_fast(dc0 * (__fdividef(diag, a) - 1.f) + dc1);
            float att = (j != i) ? e * a * sc : 0.f;
            float wgt = c0s * fmaxf(att, 0.f) + c1s * fminf(att, 0.f);
            ac += wgt * v;
        }
        if (lane < D) {
            float outv = ac + c2s * wi;
            out[(size_t)i * D + lane] = outv;
        }
    }
}

// ---------------- head: log_softmax + softmax + top2 ----------------
__global__ void k_head(const float* __restrict__ C, float* __restrict__ logp,
                       float* __restrict__ pred) {
    int g = threadIdx.x >> 4;
    int l = threadIdx.x & 15;
    int row = blockIdx.x * 16 + g;
    float x = C[row * CLS + l];
    float m = x;
#pragma unroll
    for (int o = 8; o; o >>= 1) m = fmaxf(m, __shfl_xor_sync(0xffffffffu, m, o, 16));
    float ex = expf(x - m);
    float se = ex;
#pragma unroll
    for (int o = 8; o; o >>= 1) se += __shfl_xor_sync(0xffffffffu, se, o, 16);
    float lse = logf(se);
    logp[row * CLS + l] = x - m - lse;
    float pr = ex / se;
    pred[row * CLS + l] = pr;
    int laneid = threadIdx.x & 31;
    int segbase = laneid & 16;
    float m1 = -1.f, m2 = -1.f;
#pragma unroll
    for (int k = 0; k < 16; k++) {
        float v = __shfl_sync(0xffffffffu, pr, segbase + k);
        if (v > m1) { m2 = m1; m1 = v; }
        else if (v > m2) m2 = v;
    }
    if (l == 0) g_t2[row] = m1 + m2;
}

// ---------------- deterministic calib reduction ----------------
__global__ void k_calib(float* __restrict__ out_calib) {
    __shared__ float sh[256];
    float s = 0.f;
    for (int i = threadIdx.x; i < NV; i += 256) s += g_t2[i];
    sh[threadIdx.x] = s;
    __syncthreads();
    for (int o = 128; o; o >>= 1) {
        if (threadIdx.x < o) sh[threadIdx.x] += sh[threadIdx.x + o];
        __syncthreads();
    }
    if (threadIdx.x == 0) out_calib[0] = sh[0] / (float)NV;
}

// ---------------- launcher ----------------
extern "C" void kernel_launch(void* const* d_in, const int* in_sizes, int n_in,
                              void* d_out, int out_size) {
    const float* x    = (const float*)d_in[0];
    const float* adj  = (const float*)d_in[1];
    const float* fcnW = (const float*)d_in[2];
    const float* fcnb = (const float*)d_in[3];
    const float* W0   = (const float*)d_in[4];
    const float* b0   = (const float*)d_in[5];
    const float* dc0  = (const float*)d_in[6];
    const float* c0   = (const float*)d_in[7];
    const float* s0   = (const float*)d_in[8];
    const float* W1   = (const float*)d_in[9];
    const float* b1   = (const float*)d_in[10];
    const float* dc1  = (const float*)d_in[11];
    const float* c1   = (const float*)d_in[12];
    const float* s1   = (const float*)d_in[13];
    const float* W2   = (const float*)d_in[14];
    const float* b2   = (const float*)d_in[15];
    const float* dc2  = (const float*)d_in[16];
    const float* c2   = (const float*)d_in[17];
    const float* s2   = (const float*)d_in[18];

    float* out       = (float*)d_out;
    float* out_logp  = out;
    float* out_calib = out + NV * CLS;
    float* out_pred  = out + NV * CLS + 1;

    float *pP, *pA, *pC16, *pO16;
    cudaGetSymbolAddress((void**)&pP,   g_P);
    cudaGetSymbolAddress((void**)&pA,   g_A);
    cudaGetSymbolAddress((void**)&pC16, g_C16);
    cudaGetSymbolAddress((void**)&pO16, g_O16);
    __nv_bfloat16 *pxh, *pxl, *pph, *ppl, *pwh, *pwl;
    cudaGetSymbolAddress((void**)&pxh, g_xhi);
    cudaGetSymbolAddress((void**)&pxl, g_xlo);
    cudaGetSymbolAddress((void**)&pph, g_phi);
    cudaGetSymbolAddress((void**)&ppl, g_plo);
    cudaGetSymbolAddress((void**)&pwh, g_whi);
    cudaGetSymbolAddress((void**)&pwl, g_wlo);

    cudaFuncSetAttribute(k_mma_gemm, cudaFuncAttributeMaxDynamicSharedMemorySize, F_SMEM);

    // 0: fused splits (x, fcnW, W0, W1)
    k_prep<<<(NX4 + 2 * NW4 + NW14 + 255) / 256, 256>>>(x, fcnW, W0, W1,
                                                        pxh, pxl, pwh, pwl);

    // 1: merged GEMM: prev = elu(x@fcnW^T+fcnb)  AND  Wh0 = x@W0^T+b0 (+norm partials)
    k_mma_gemm<<<dim3(NV / 128, 4), 256, F_SMEM>>>(pxh, pxl, pwh, pwl,
                                                   fcnb, b0, pP, pA, FEAT, 2);

    // 2: CSR from adjacency (also extracts diag)
    k_build_csr<<<NV, 256>>>(adj);

    // 3: layer 0 sparse (warp-per-row): residual into P + bf16 split of new P
    k_sparse<HID, true, true><<<NV / 8, 256>>>(pA, pP, dc0, c0, s0, 1.0f, pph, ppl);

    // ---- layer 1 (input prev; W1 already split at offset W1_OFF) ----
    k_mma_gemm<<<dim3(NV / 128, 2), 256, F_SMEM>>>(pph, ppl, pwh + W1_OFF, pwl + W1_OFF,
                                                   b1, b1, pA, pA, HID, 0);
    float decay = (float)log(0.9 / 27.0 + 1.0);
    k_sparse<HID, true, false><<<NV / 8, 256>>>(pA, pP, dc1, c1, s1, decay, pph, ppl);

    // ---- layer 2 (input prev, D=16; norm fused into small GEMM) ----
    k_gemm_small<<<NV / 8, 256>>>(pP, W2, b2, pC16, NV, CLS, HID);
    k_sparse<CLS, false, false><<<NV / 8, 256>>>(pC16, pO16, dc2, c2, s2, 0.0f, pph, ppl);

    // ---- head ----
    k_head<<<NV / 16, 256>>>(pO16, out_logp, out_pred);
    k_calib<<<1, 256>>>(out_calib);
}